// round 12
// baseline (speedup 1.0000x reference)
#include <cuda_runtime.h>
#include <cstdint>

// PoolingLayer: out[p, f] = max_k features[idx[p,k], f]
// NP=50000, K=32, F=128. features: (100000,128) f32. idx: (50000,32) int32.
//
// Roofline model (R5-R11): gather delivers ~17.6TB/s total, above the ~12.6TB/s
// LTS cap -> ~30-40% of bytes come from L1 hits (each row read ~16x chip-wide).
// __ldcg (R11) removed those hits and regressed; keep .ca (__ldg).
// This round de-confounds R11: R9 structure + 8 blocks/SM (32 regs = full RF).

#define NP_POINTS 50000
#define N_POINTS  100000
#define K_NEIGH   32
#define F_VEC4    32   // 128 floats = 32 float4
#define BATCH     4

#define SZ_FEATURES 12800000   // 100000 * 128 f32
#define SZ_INDICES  1600000    // 50000 * 32

__global__ __launch_bounds__(256, 8)
void pool_max_kernel(const float4* __restrict__ feat,
                     const int* __restrict__ idx,
                     float4* __restrict__ out)
{
    const int gtid = blockIdx.x * blockDim.x + threadIdx.x;
    const int warp = gtid >> 5;
    const int lane = gtid & 31;
    if (warp >= NP_POINTS) return;

    // Coalesced, read-once index load.
    int my_idx = __ldcs(&idx[warp * K_NEIGH + lane]);
    // Clamp: a format surprise becomes rel_err, never an illegal access.
    my_idx = min(max(my_idx, 0), N_POINTS - 1);

    const float NEG_INF = -__int_as_float(0x7f800000);
    float4 m = make_float4(NEG_INF, NEG_INF, NEG_INF, NEG_INF);

    #pragma unroll
    for (int kb = 0; kb < K_NEIGH / BATCH; ++kb) {
        // Phase 1: 4 independent gathers in flight (MLP=4), L1-cached (.ca):
        // ~30-40% of gather bytes are served by L1 re-hits.
        float4 v[BATCH];
        #pragma unroll
        for (int u = 0; u < BATCH; ++u) {
            const int j = __shfl_sync(0xffffffffu, my_idx, kb * BATCH + u);
            v[u] = __ldg(&feat[(long long)j * F_VEC4 + lane]);
        }
        // Phase 2: pairwise fold tree, then into the accumulator.
        float4 a, b;
        a.x = fmaxf(v[0].x, v[1].x);  b.x = fmaxf(v[2].x, v[3].x);
        a.y = fmaxf(v[0].y, v[1].y);  b.y = fmaxf(v[2].y, v[3].y);
        a.z = fmaxf(v[0].z, v[1].z);  b.z = fmaxf(v[2].z, v[3].z);
        a.w = fmaxf(v[0].w, v[1].w);  b.w = fmaxf(v[2].w, v[3].w);
        m.x = fmaxf(m.x, fmaxf(a.x, b.x));
        m.y = fmaxf(m.y, fmaxf(a.y, b.y));
        m.z = fmaxf(m.z, fmaxf(a.z, b.z));
        m.w = fmaxf(m.w, fmaxf(a.w, b.w));
    }

    // Write-once output: streaming store, don't pollute L2.
    __stcs(&out[(long long)warp * F_VEC4 + lane], m);
}

extern "C" void kernel_launch(void* const* d_in, const int* in_sizes, int n_in,
                              void* d_out, int out_size)
{
    // Resolve inputs by element count (order-independent):
    //   features : 12800000 f32
    //   indices  : 1600000 int32
    const float4* feat = nullptr;
    const int*    idx  = nullptr;
    for (int i = 0; i < n_in; ++i) {
        if (in_sizes[i] == SZ_FEATURES)     feat = (const float4*)d_in[i];
        else if (in_sizes[i] == SZ_INDICES) idx  = (const int*)d_in[i];
    }
    if (!feat) feat = (const float4*)d_in[1];
    if (!idx)  idx  = (const int*)d_in[2];

    float4* out = (float4*)d_out;

    const int total_threads = NP_POINTS * 32;   // one warp per point
    const int block = 256;
    const int grid = (total_threads + block - 1) / block;  // 6250
    pool_max_kernel<<<grid, block>>>(feat, idx, out);
}

// round 13
// speedup vs baseline: 1.0860x; 1.0860x over previous
#include <cuda_runtime.h>
#include <cstdint>

// PoolingLayer: out[p, f] = max_k features[idx[p,k], f]
// NP=50000, K=32, F=128. features: (100000,128) f32. idx: (50000,32) int32.
//
// FINAL (R9 config — measured best). Roofline analysis across R5-R12:
// random 512B-row gather delivers ~17.6TB/s (L2 cap ~12.6TB/s + ~5TB/s L1
// re-hits); kernel ncu-dur is invariant at ~46.5us across occ 43-93%,
// MLP 2-8, LDG.64/128 -> this is the L1+LTS service floor for the pattern.
// 1 warp per output point; lane l owns float4 #l (512B/row fully coalesced);
// 4 gathers in flight; pairwise fmax fold; streaming idx load + out store.

#define NP_POINTS 50000
#define N_POINTS  100000
#define K_NEIGH   32
#define F_VEC4    32   // 128 floats = 32 float4
#define BATCH     4

#define SZ_FEATURES 12800000   // 100000 * 128 f32
#define SZ_INDICES  1600000    // 50000 * 32

__global__ __launch_bounds__(256, 7)
void pool_max_kernel(const float4* __restrict__ feat,
                     const int* __restrict__ idx,
                     float4* __restrict__ out)
{
    const int gtid = blockIdx.x * blockDim.x + threadIdx.x;
    const int warp = gtid >> 5;
    const int lane = gtid & 31;
    if (warp >= NP_POINTS) return;

    // Coalesced, read-once index load.
    int my_idx = __ldcs(&idx[warp * K_NEIGH + lane]);
    // Clamp: a format surprise becomes rel_err, never an illegal access.
    my_idx = min(max(my_idx, 0), N_POINTS - 1);

    const float NEG_INF = -__int_as_float(0x7f800000);
    float4 m = make_float4(NEG_INF, NEG_INF, NEG_INF, NEG_INF);

    #pragma unroll
    for (int kb = 0; kb < K_NEIGH / BATCH; ++kb) {
        // Phase 1: 4 independent gathers in flight (MLP=4), L1-cached (.ca):
        // a large fraction of gather bytes is served by L1 re-hits.
        float4 v[BATCH];
        #pragma unroll
        for (int u = 0; u < BATCH; ++u) {
            const int j = __shfl_sync(0xffffffffu, my_idx, kb * BATCH + u);
            v[u] = __ldg(&feat[(long long)j * F_VEC4 + lane]);
        }
        // Phase 2: pairwise fold tree, then into the accumulator.
        float4 a, b;
        a.x = fmaxf(v[0].x, v[1].x);  b.x = fmaxf(v[2].x, v[3].x);
        a.y = fmaxf(v[0].y, v[1].y);  b.y = fmaxf(v[2].y, v[3].y);
        a.z = fmaxf(v[0].z, v[1].z);  b.z = fmaxf(v[2].z, v[3].z);
        a.w = fmaxf(v[0].w, v[1].w);  b.w = fmaxf(v[2].w, v[3].w);
        m.x = fmaxf(m.x, fmaxf(a.x, b.x));
        m.y = fmaxf(m.y, fmaxf(a.y, b.y));
        m.z = fmaxf(m.z, fmaxf(a.z, b.z));
        m.w = fmaxf(m.w, fmaxf(a.w, b.w));
    }

    // Write-once output: streaming store, don't pollute L2.
    __stcs(&out[(long long)warp * F_VEC4 + lane], m);
}

extern "C" void kernel_launch(void* const* d_in, const int* in_sizes, int n_in,
                              void* d_out, int out_size)
{
    // Resolve inputs by element count (order-independent):
    //   features : 12800000 f32
    //   indices  : 1600000 int32
    const float4* feat = nullptr;
    const int*    idx  = nullptr;
    for (int i = 0; i < n_in; ++i) {
        if (in_sizes[i] == SZ_FEATURES)     feat = (const float4*)d_in[i];
        else if (in_sizes[i] == SZ_INDICES) idx  = (const int*)d_in[i];
    }
    if (!feat) feat = (const float4*)d_in[1];
    if (!idx)  idx  = (const int*)d_in[2];

    float4* out = (float4*)d_out;

    const int total_threads = NP_POINTS * 32;   // one warp per point
    const int block = 256;
    const int grid = (total_threads + block - 1) / block;  // 6250
    pool_max_kernel<<<grid, block>>>(feat, idx, out);
}

// round 14
// speedup vs baseline: 1.1178x; 1.0293x over previous
#include <cuda_runtime.h>
#include <cstdint>

// PoolingLayer: out[p, f] = max_k features[idx[p,k], f]
// NP=50000, K=32, F=128. features: (100000,128) f32. idx: (50000,32) int32.
//
// Roofline (R5-R13): random 512B-row gather sits at the combined L1-rehit +
// LTS service floor (~17.5TB/s delivered; ncu dur invariant at 46.4-47.7us
// across occ 43-93%, MLP 2-8, LDG.64/128, .ca/.cg). Final untested axis:
// CTA granularity. block=128 @ 14 blocks/SM keeps 56 warps/SM but halves the
// per-CTA front-batched gather burst (32 vs 64 LDGs) and doubles wave
// granularity -> smoother L1tex queue / tail, per the B300 spread model.
// Kernel body identical to the proven-best R9 structure.

#define NP_POINTS 50000
#define N_POINTS  100000
#define K_NEIGH   32
#define F_VEC4    32   // 128 floats = 32 float4
#define BATCH     4

#define SZ_FEATURES 12800000   // 100000 * 128 f32
#define SZ_INDICES  1600000    // 50000 * 32

__global__ __launch_bounds__(128, 14)
void pool_max_kernel(const float4* __restrict__ feat,
                     const int* __restrict__ idx,
                     float4* __restrict__ out)
{
    const int gtid = blockIdx.x * blockDim.x + threadIdx.x;
    const int warp = gtid >> 5;
    const int lane = gtid & 31;
    if (warp >= NP_POINTS) return;

    // Coalesced, read-once index load.
    int my_idx = __ldcs(&idx[warp * K_NEIGH + lane]);
    // Clamp: a format surprise becomes rel_err, never an illegal access.
    my_idx = min(max(my_idx, 0), N_POINTS - 1);

    const float NEG_INF = -__int_as_float(0x7f800000);
    float4 m = make_float4(NEG_INF, NEG_INF, NEG_INF, NEG_INF);

    #pragma unroll
    for (int kb = 0; kb < K_NEIGH / BATCH; ++kb) {
        // Phase 1: 4 independent gathers in flight (MLP=4), L1-cached (.ca):
        // a large fraction of gather bytes is served by L1 re-hits.
        float4 v[BATCH];
        #pragma unroll
        for (int u = 0; u < BATCH; ++u) {
            const int j = __shfl_sync(0xffffffffu, my_idx, kb * BATCH + u);
            v[u] = __ldg(&feat[(long long)j * F_VEC4 + lane]);
        }
        // Phase 2: pairwise fold tree, then into the accumulator.
        float4 a, b;
        a.x = fmaxf(v[0].x, v[1].x);  b.x = fmaxf(v[2].x, v[3].x);
        a.y = fmaxf(v[0].y, v[1].y);  b.y = fmaxf(v[2].y, v[3].y);
        a.z = fmaxf(v[0].z, v[1].z);  b.z = fmaxf(v[2].z, v[3].z);
        a.w = fmaxf(v[0].w, v[1].w);  b.w = fmaxf(v[2].w, v[3].w);
        m.x = fmaxf(m.x, fmaxf(a.x, b.x));
        m.y = fmaxf(m.y, fmaxf(a.y, b.y));
        m.z = fmaxf(m.z, fmaxf(a.z, b.z));
        m.w = fmaxf(m.w, fmaxf(a.w, b.w));
    }

    // Write-once output: streaming store, don't pollute L2.
    __stcs(&out[(long long)warp * F_VEC4 + lane], m);
}

extern "C" void kernel_launch(void* const* d_in, const int* in_sizes, int n_in,
                              void* d_out, int out_size)
{
    // Resolve inputs by element count (order-independent):
    //   features : 12800000 f32
    //   indices  : 1600000 int32
    const float4* feat = nullptr;
    const int*    idx  = nullptr;
    for (int i = 0; i < n_in; ++i) {
        if (in_sizes[i] == SZ_FEATURES)     feat = (const float4*)d_in[i];
        else if (in_sizes[i] == SZ_INDICES) idx  = (const int*)d_in[i];
    }
    if (!feat) feat = (const float4*)d_in[1];
    if (!idx)  idx  = (const int*)d_in[2];

    float4* out = (float4*)d_out;

    const int total_threads = NP_POINTS * 32;   // one warp per point
    const int block = 128;
    const int grid = (total_threads + block - 1) / block;  // 12500
    pool_max_kernel<<<grid, block>>>(feat, idx, out);
}